// round 1
// baseline (speedup 1.0000x reference)
#include <cuda_runtime.h>
#include <math.h>

// Problem constants
#define BB 2
#define SS 2048
#define FF 512
#define II 1024
#define CC 256

// ---------------- scratch (device globals; no allocation allowed) ----------
__device__ float g_a[BB*SS*FF];
__device__ float g_b[BB*SS*FF];
__device__ float g_h[BB*SS*FF];
__device__ float g_t1[BB*SS*II];
__device__ float g_t2[BB*SS*II];
__device__ float g_d[BB*SS*FF];
__device__ float g_sc[BB*SS*FF];
__device__ float g_sh[BB*SS*FF];
__device__ float g_str[BB*SS*2*FF];
__device__ float g_logits[BB*SS*CC];
__device__ float g_nll[BB*SS];

// ---------------- embedding gather: a = emb[inp][:, :F], b = emb[inp][:, F:]
__global__ void embed_kernel(const int* __restrict__ inp,
                             const float* __restrict__ emb) {
    int idx = blockIdx.x * 256 + threadIdx.x;
    if (idx >= BB*SS*2*FF) return;
    int bs = idx / (2*FF);
    int j  = idx - bs * (2*FF);
    int row = inp[bs];
    float v = emb[(size_t)row * (2*FF) + j];
    if (j < FF) g_a[(size_t)bs*FF + j] = v;
    else        g_b[(size_t)bs*FF + (j - FF)] = v;
}

// ---------------- h = b + feature_embd(f) --------------------------------
__global__ void h_kernel() {
    int idx = blockIdx.x * 256 + threadIdx.x;
    if (idx >= BB*SS*FF) return;
    int f = idx & (FF - 1);
    float f1 = (float)(f + 1);
    float additive = ((f + 1) & 1) ? 1.0f : 0.0f;       // (f+1) % 2
    float f2 = (f1 - additive) * 0.5f;
    // log(C / (2*pi)) = log(256 / 6.283185307179586) = 3.707301010157416
    float f3 = f2 * (8.0f / (float)FF) - 3.707301010157416f;
    float fe = expf(f3) + additive * 3.14159265358979f;
    g_h[idx] = g_b[idx] + fe;
}

// ---------------- tiled conv-GEMM ----------------------------------------
// y[b,s,o] = act( sum_{c,kk} W[o,c,kk] * x[b, s+kk-(KW-1), c] ) (+bias)
// x: (B,S,CIN) row-major, W: (COUT,CIN,KW) row-major, y: (B,S,COUT)
// Reduction index r = kk*CIN + c (kk-major: keeps x loads coalesced for KW=3)
template<int CIN, int COUT, int KW, bool RELU, bool BIAS>
__global__ void conv_gemm(const float* __restrict__ x,
                          const float* __restrict__ w,
                          const float* __restrict__ bias,
                          float* __restrict__ y) {
    constexpr int R = CIN * KW;
    const int s0 = blockIdx.x * 64;      // S tile
    const int o0 = blockIdx.y * 64;      // COUT tile
    const int bq = blockIdx.z;
    const float* xb = x + (size_t)bq * SS * CIN;
    float* yb = y + (size_t)bq * SS * COUT;

    __shared__ float Xs[64][17];   // [s_local][r_local], padded
    __shared__ float Ws[64][17];   // [o_local][r_local], padded

    const int tid = threadIdx.x;        // 256 threads
    const int tx = tid & 15;            // -> output channel lane
    const int ty = tid >> 4;            // -> s lane

    float acc[4][4];
    #pragma unroll
    for (int i = 0; i < 4; i++)
        #pragma unroll
        for (int j = 0; j < 4; j++) acc[i][j] = 0.0f;

    for (int r0 = 0; r0 < R; r0 += 16) {
        #pragma unroll
        for (int u = 0; u < 4; u++) {
            int idx = tid + u * 256;    // 0..1023
            int ri = idx & 15;
            int m  = idx >> 4;          // 0..63
            int rr = r0 + ri;
            int kk = rr / CIN;          // compile-time shift
            int c  = rr - kk * CIN;
            int ss = s0 + m + kk - (KW - 1);
            Xs[m][ri] = (ss >= 0) ? xb[(size_t)ss * CIN + c] : 0.0f;
            Ws[m][ri] = w[(size_t)(o0 + m) * R + (size_t)c * KW + kk];
        }
        __syncthreads();
        #pragma unroll
        for (int r = 0; r < 16; r++) {
            float av[4], bv[4];
            #pragma unroll
            for (int i = 0; i < 4; i++) av[i] = Ws[tx + 16*i][r];
            #pragma unroll
            for (int j = 0; j < 4; j++) bv[j] = Xs[ty + 16*j][r];
            #pragma unroll
            for (int i = 0; i < 4; i++)
                #pragma unroll
                for (int j = 0; j < 4; j++)
                    acc[i][j] = fmaf(av[i], bv[j], acc[i][j]);
        }
        __syncthreads();
    }

    #pragma unroll
    for (int j = 0; j < 4; j++) {
        int sI = s0 + ty + 16*j;
        #pragma unroll
        for (int i = 0; i < 4; i++) {
            int o = o0 + tx + 16*i;
            float v = acc[i][j];
            if (BIAS) v += bias[o];
            if (RELU) v = fmaxf(v, 0.0f);
            yb[(size_t)sI * COUT + o] = v;
        }
    }
}

// ---------------- cell update: cumsum over channels, norm, EMA -----------
// One block per (b,s): 512 threads, one per channel f.
__global__ void cell_kernel() {
    int bs = blockIdx.x;                  // 0..B*S-1
    int s  = bs & (SS - 1);
    int f  = threadIdx.x;                 // 0..511
    size_t base = (size_t)bs * FF;

    float v = g_d[base + f];

    // inclusive scan over 512 channels
    int lane = f & 31, wp = f >> 5;
    #pragma unroll
    for (int off = 1; off < 32; off <<= 1) {
        float n = __shfl_up_sync(0xffffffffu, v, off);
        if (lane >= off) v += n;
    }
    __shared__ float wsum[16];
    __shared__ float red1[16], red2[16];
    __shared__ float bc[2];
    if (lane == 31) wsum[wp] = v;
    __syncthreads();
    if (f < 16) {
        float t = wsum[f];
        #pragma unroll
        for (int off = 1; off < 16; off <<= 1) {
            float n = __shfl_up_sync(0x0000ffffu, t, off);
            if (f >= off) t += n;
        }
        wsum[f] = t;
    }
    __syncthreads();
    float cum = v + (wp > 0 ? wsum[wp - 1] : 0.0f);

    float val = cum / (float)(s + 1) * g_sc[base + f] + g_sh[base + f];

    // block reductions: sum and sum of squares
    float s1 = val, s2 = val * val;
    #pragma unroll
    for (int off = 16; off > 0; off >>= 1) {
        s1 += __shfl_down_sync(0xffffffffu, s1, off);
        s2 += __shfl_down_sync(0xffffffffu, s2, off);
    }
    if (lane == 0) { red1[wp] = s1; red2[wp] = s2; }
    __syncthreads();
    if (f == 0) {
        float t1 = 0.0f, t2 = 0.0f;
        #pragma unroll
        for (int i = 0; i < 16; i++) { t1 += red1[i]; t2 += red2[i]; }
        bc[0] = t1; bc[1] = t2;
    }
    __syncthreads();
    float tot = bc[0], totsq = bc[1];

    float mean = tot * (1.0f / FF);
    float var  = totsq - tot * tot * (1.0f / FF);   // sum((x-mean)^2)
    float l2   = sqrtf(fmaxf(var, 0.0f));
    // F^{-1/2} = 1/sqrt(512)
    float denom = l2 * 0.04419417382415922f + 1e-5f;
    float cell = (val - mean) / denom * 0.7071067811865476f;  // * L^{-1/2}

    float an = 0.99f * g_a[base + f] + 0.01f * cell;
    g_a[base + f] = an;
    g_b[base + f] += an;
}

// ---------------- streams = concat([a, b], channel) ----------------------
__global__ void concat_kernel() {
    int idx = blockIdx.x * 256 + threadIdx.x;
    if (idx >= BB*SS*2*FF) return;
    int bs = idx / (2*FF);
    int j  = idx - bs * (2*FF);
    g_str[idx] = (j < FF) ? g_a[(size_t)bs*FF + j]
                          : g_b[(size_t)bs*FF + (j - FF)];
}

// ---------------- log_softmax over C + NLL gather (one warp per row) -----
__global__ void nll_kernel(const int* __restrict__ tgt) {
    int row = blockIdx.x * 8 + (threadIdx.x >> 5);
    int lane = threadIdx.x & 31;
    if (row >= BB*SS) return;
    const float* lr = g_logits + (size_t)row * CC;

    float vals[8];
    float vmax = -1e30f;
    #pragma unroll
    for (int k = 0; k < 8; k++) {
        vals[k] = lr[lane + 32*k];
        vmax = fmaxf(vmax, vals[k]);
    }
    #pragma unroll
    for (int off = 16; off > 0; off >>= 1)
        vmax = fmaxf(vmax, __shfl_xor_sync(0xffffffffu, vmax, off));

    float se = 0.0f;
    #pragma unroll
    for (int k = 0; k < 8; k++) se += expf(vals[k] - vmax);
    #pragma unroll
    for (int off = 16; off > 0; off >>= 1)
        se += __shfl_xor_sync(0xffffffffu, se, off);

    float logZ = vmax + logf(se);
    if (lane == 0) g_nll[row] = logZ - lr[tgt[row]];
}

// ---------------- deterministic final mean -------------------------------
__global__ void reduce_kernel(float* __restrict__ out) {
    __shared__ float sm[256];
    float acc = 0.0f;
    for (int i = threadIdx.x; i < BB*SS; i += 256) acc += g_nll[i];
    sm[threadIdx.x] = acc;
    __syncthreads();
    for (int st = 128; st > 0; st >>= 1) {
        if (threadIdx.x < st) sm[threadIdx.x] += sm[threadIdx.x + st];
        __syncthreads();
    }
    if (threadIdx.x == 0) out[0] = sm[0] / (float)(BB*SS);
}

// ---------------- launcher ----------------------------------------------
extern "C" void kernel_launch(void* const* d_in, const int* in_sizes, int n_in,
                              void* d_out, int out_size) {
    const int*   inp   = (const int*)  d_in[0];
    const int*   tgt   = (const int*)  d_in[1];
    const float* emb   = (const float*)d_in[2];
    const float* w0s   = (const float*)d_in[3];   // (L,3,I,F,1)
    const float* w1s   = (const float*)d_in[4];   // (L,3,I,I,3)
    const float* w2s   = (const float*)d_in[5];   // (L,3,F,I,1)
    const float* out_w = (const float*)d_in[6];   // (C,2F,1)
    const float* out_b = (const float*)d_in[7];   // (C,)
    float* out = (float*)d_out;

    float *ph, *pt1, *pt2, *pd, *psc, *psh, *pstr, *plog;
    cudaGetSymbolAddress((void**)&ph,   g_h);
    cudaGetSymbolAddress((void**)&pt1,  g_t1);
    cudaGetSymbolAddress((void**)&pt2,  g_t2);
    cudaGetSymbolAddress((void**)&pd,   g_d);
    cudaGetSymbolAddress((void**)&psc,  g_sc);
    cudaGetSymbolAddress((void**)&psh,  g_sh);
    cudaGetSymbolAddress((void**)&pstr, g_str);
    cudaGetSymbolAddress((void**)&plog, g_logits);

    embed_kernel<<<(BB*SS*2*FF + 255)/256, 256>>>(inp, emb);

    float* dests[3] = {pd, psc, psh};
    for (int l = 0; l < 2; l++) {
        h_kernel<<<(BB*SS*FF + 255)/256, 256>>>();
        for (int j = 0; j < 3; j++) {
            const float* w0 = w0s + (size_t)(l*3 + j) * II * FF;
            const float* w1 = w1s + (size_t)(l*3 + j) * II * II * 3;
            const float* w2 = w2s + (size_t)(l*3 + j) * FF * II;
            conv_gemm<FF, II, 1, true,  false>
                <<<dim3(SS/64, II/64, BB), 256>>>(ph,  w0, nullptr, pt1);
            conv_gemm<II, II, 3, true,  false>
                <<<dim3(SS/64, II/64, BB), 256>>>(pt1, w1, nullptr, pt2);
            conv_gemm<II, FF, 1, false, false>
                <<<dim3(SS/64, FF/64, BB), 256>>>(pt2, w2, nullptr, dests[j]);
        }
        cell_kernel<<<BB*SS, FF>>>();
    }

    concat_kernel<<<(BB*SS*2*FF + 255)/256, 256>>>();
    conv_gemm<2*FF, CC, 1, false, true>
        <<<dim3(SS/64, CC/64, BB), 256>>>(pstr, out_w, out_b, plog);

    nll_kernel<<<(BB*SS)/8, 256>>>(tgt);
    reduce_kernel<<<1, 256>>>(out);
}

// round 4
// speedup vs baseline: 1.5240x; 1.5240x over previous
#include <cuda_runtime.h>
#include <math.h>

// Problem constants
#define BB 2
#define SS 2048
#define FF 512
#define II 1024
#define CC 256

// ---------------- scratch (device globals; no allocation allowed) ----------
__device__ float g_a[BB*SS*FF];
__device__ float g_b[BB*SS*FF];
__device__ float g_h[BB*SS*FF];
__device__ float g_t1[BB*SS*II];
__device__ float g_t2[BB*SS*II];
__device__ float g_d[BB*SS*FF];
__device__ float g_sc[BB*SS*FF];
__device__ float g_sh[BB*SS*FF];
__device__ float g_str[BB*SS*2*FF];
__device__ float g_logits[BB*SS*CC];
__device__ float g_nll[BB*SS];

// transposed weights: Wt[kk*CIN + c][o]  (row-major (R, COUT))
__device__ float g_w0t[2*3*II*FF];        // 6 * 524288
__device__ float g_w1t[2*3*II*II*3];      // 6 * 3145728
__device__ float g_w2t[2*3*FF*II];        // 6 * 524288

// ---------------- weight transpose: Wt[(kk*CIN+c)*COUT+o] = W[(o*CIN+c)*KW+kk]
__global__ void transpose_w(const float* __restrict__ w, float* __restrict__ wt,
                            int COUT, int CIN, int KW) {
    long idx = (long)blockIdx.x * 256 + threadIdx.x;
    long total = (long)COUT * CIN * KW;
    if (idx >= total) return;
    int o = (int)(idx % COUT);
    long rc = idx / COUT;
    int c = (int)(rc % CIN);
    int kk = (int)(rc / CIN);
    wt[idx] = w[((long)o * CIN + c) * KW + kk];
}

// ---------------- embedding gather ---------------------------------------
__global__ void embed_kernel(const int* __restrict__ inp,
                             const float* __restrict__ emb) {
    int idx = blockIdx.x * 256 + threadIdx.x;
    if (idx >= BB*SS*2*FF) return;
    int bs = idx / (2*FF);
    int j  = idx - bs * (2*FF);
    int row = inp[bs];
    float v = emb[(size_t)row * (2*FF) + j];
    if (j < FF) g_a[(size_t)bs*FF + j] = v;
    else        g_b[(size_t)bs*FF + (j - FF)] = v;
}

// ---------------- h = b + feature_embd(f) --------------------------------
__global__ void h_kernel() {
    int idx = blockIdx.x * 256 + threadIdx.x;
    if (idx >= BB*SS*FF) return;
    int f = idx & (FF - 1);
    float f1 = (float)(f + 1);
    float additive = ((f + 1) & 1) ? 1.0f : 0.0f;
    float f2 = (f1 - additive) * 0.5f;
    float f3 = f2 * (8.0f / (float)FF) - 3.707301010157416f; // log(C/(2pi))
    float fe = expf(f3) + additive * 3.14159265358979f;
    g_h[idx] = g_b[idx] + fe;
}

// ---------------- big tiled conv-GEMM (128x128x8, 8x8 per thread) --------
// y[b,s,o] = act( sum_r Wt[r][o] * x[b, s + r/CIN - (KW-1), r%CIN] )
// x: (B,S,CIN) row-major, wt: (KW*CIN, COUT) row-major, y: (B,S,COUT)
template<int CIN, int COUT, int KW, bool RELU>
__global__ __launch_bounds__(256, 2)
void conv_gemm128(const float* __restrict__ x,
                  const float* __restrict__ wt,
                  float* __restrict__ y) {
    constexpr int R = CIN * KW;
    constexpr int NIT = R / 8;
    const int s0 = blockIdx.x * 128;
    const int o0 = blockIdx.y * 128;
    const int bq = blockIdx.z;
    const float* xb = x + (size_t)bq * SS * CIN;
    float* yb = y + (size_t)bq * SS * COUT;

    __shared__ float As[8][132];   // [r_local][m], padded (528B rows, 16B-aligned)
    __shared__ float Bs[8][128];   // [r_local][o_local]

    const int tid = threadIdx.x;   // 256 threads
    const int tx = tid & 15;       // output-channel lane
    const int ty = tid >> 4;       // s lane

    // global-load indices
    const int am = tid >> 1;           // 0..127   X row within tile
    const int aq = (tid & 1) * 4;      // col group 0 or 4
    const int br = tid >> 5;           // 0..7     Wt row within tile
    const int bo = (tid & 31) * 4;     // 0..124

    float4 xreg, wreg;
    float acc[8][8];
    #pragma unroll
    for (int i = 0; i < 8; i++)
        #pragma unroll
        for (int j = 0; j < 8; j++) acc[i][j] = 0.0f;

#define LDG_TILE(ITV) do {                                                   \
        int r0_ = (ITV) * 8;                                                 \
        int kk_ = r0_ / CIN;                                                 \
        int c0_ = r0_ - kk_ * CIN;                                           \
        int ssx_ = s0 + am + kk_ - (KW - 1);                                 \
        if (ssx_ >= 0)                                                       \
            xreg = *(const float4*)&xb[(size_t)ssx_ * CIN + c0_ + aq];       \
        else xreg = make_float4(0.f, 0.f, 0.f, 0.f);                         \
        wreg = *(const float4*)&wt[(size_t)(r0_ + br) * COUT + o0 + bo];     \
    } while (0)

    LDG_TILE(0);
    for (int it = 0; it < NIT; ++it) {
        // stage to smem (A transposed)
        As[aq + 0][am] = xreg.x;
        As[aq + 1][am] = xreg.y;
        As[aq + 2][am] = xreg.z;
        As[aq + 3][am] = xreg.w;
        *(float4*)&Bs[br][bo] = wreg;
        __syncthreads();
        if (it + 1 < NIT) LDG_TILE(it + 1);
        #pragma unroll
        for (int r = 0; r < 8; ++r) {
            float4 a0 = *(const float4*)&As[r][ty * 4];
            float4 a1 = *(const float4*)&As[r][64 + ty * 4];
            float4 b0 = *(const float4*)&Bs[r][tx * 4];
            float4 b1 = *(const float4*)&Bs[r][64 + tx * 4];
            float av[8] = {a0.x, a0.y, a0.z, a0.w, a1.x, a1.y, a1.z, a1.w};
            float bv[8] = {b0.x, b0.y, b0.z, b0.w, b1.x, b1.y, b1.z, b1.w};
            #pragma unroll
            for (int i = 0; i < 8; i++)
                #pragma unroll
                for (int j = 0; j < 8; j++)
                    acc[i][j] = fmaf(av[i], bv[j], acc[i][j]);
        }
        __syncthreads();
    }
#undef LDG_TILE

    #pragma unroll
    for (int i = 0; i < 8; i++) {
        int m = s0 + ((i < 4) ? (ty * 4 + i) : (64 + ty * 4 + i - 4));
        #pragma unroll
        for (int jg = 0; jg < 2; jg++) {
            int o = o0 + (jg ? (64 + tx * 4) : (tx * 4));
            float4 v;
            v.x = acc[i][jg * 4 + 0];
            v.y = acc[i][jg * 4 + 1];
            v.z = acc[i][jg * 4 + 2];
            v.w = acc[i][jg * 4 + 3];
            if (RELU) {
                v.x = fmaxf(v.x, 0.f); v.y = fmaxf(v.y, 0.f);
                v.z = fmaxf(v.z, 0.f); v.w = fmaxf(v.w, 0.f);
            }
            *(float4*)&yb[(size_t)m * COUT + o] = v;
        }
    }
}

// ---------------- small 64x64 conv-GEMM (kept for the final output GEMM) -
template<int CIN, int COUT, int KW, bool RELU, bool BIAS>
__global__ void conv_gemm(const float* __restrict__ x,
                          const float* __restrict__ w,
                          const float* __restrict__ bias,
                          float* __restrict__ y) {
    constexpr int R = CIN * KW;
    const int s0 = blockIdx.x * 64;
    const int o0 = blockIdx.y * 64;
    const int bq = blockIdx.z;
    const float* xb = x + (size_t)bq * SS * CIN;
    float* yb = y + (size_t)bq * SS * COUT;

    __shared__ float Xs[64][17];
    __shared__ float Ws[64][17];

    const int tid = threadIdx.x;
    const int tx = tid & 15;
    const int ty = tid >> 4;

    float acc[4][4];
    #pragma unroll
    for (int i = 0; i < 4; i++)
        #pragma unroll
        for (int j = 0; j < 4; j++) acc[i][j] = 0.0f;

    for (int r0 = 0; r0 < R; r0 += 16) {
        #pragma unroll
        for (int u = 0; u < 4; u++) {
            int idx = tid + u * 256;
            int ri = idx & 15;
            int m  = idx >> 4;
            int rr = r0 + ri;
            int kk = rr / CIN;
            int c  = rr - kk * CIN;
            int ss = s0 + m + kk - (KW - 1);
            Xs[m][ri] = (ss >= 0) ? xb[(size_t)ss * CIN + c] : 0.0f;
            Ws[m][ri] = w[(size_t)(o0 + m) * R + (size_t)c * KW + kk];
        }
        __syncthreads();
        #pragma unroll
        for (int r = 0; r < 16; r++) {
            float av[4], bv[4];
            #pragma unroll
            for (int i = 0; i < 4; i++) av[i] = Ws[tx + 16*i][r];
            #pragma unroll
            for (int j = 0; j < 4; j++) bv[j] = Xs[ty + 16*j][r];
            #pragma unroll
            for (int i = 0; i < 4; i++)
                #pragma unroll
                for (int j = 0; j < 4; j++)
                    acc[i][j] = fmaf(av[i], bv[j], acc[i][j]);
        }
        __syncthreads();
    }

    #pragma unroll
    for (int j = 0; j < 4; j++) {
        int sI = s0 + ty + 16*j;
        #pragma unroll
        for (int i = 0; i < 4; i++) {
            int o = o0 + tx + 16*i;
            float v = acc[i][j];
            if (BIAS) v += bias[o];
            if (RELU) v = fmaxf(v, 0.0f);
            yb[(size_t)sI * COUT + o] = v;
        }
    }
}

// ---------------- cell update: cumsum over channels, norm, EMA -----------
__global__ void cell_kernel() {
    int bs = blockIdx.x;
    int s  = bs & (SS - 1);
    int f  = threadIdx.x;
    size_t base = (size_t)bs * FF;

    float v = g_d[base + f];

    int lane = f & 31, wp = f >> 5;
    #pragma unroll
    for (int off = 1; off < 32; off <<= 1) {
        float n = __shfl_up_sync(0xffffffffu, v, off);
        if (lane >= off) v += n;
    }
    __shared__ float wsum[16];
    __shared__ float red1[16], red2[16];
    __shared__ float bc[2];
    if (lane == 31) wsum[wp] = v;
    __syncthreads();
    if (f < 16) {
        float t = wsum[f];
        #pragma unroll
        for (int off = 1; off < 16; off <<= 1) {
            float n = __shfl_up_sync(0x0000ffffu, t, off);
            if (f >= off) t += n;
        }
        wsum[f] = t;
    }
    __syncthreads();
    float cum = v + (wp > 0 ? wsum[wp - 1] : 0.0f);

    float val = cum / (float)(s + 1) * g_sc[base + f] + g_sh[base + f];

    float s1 = val, s2 = val * val;
    #pragma unroll
    for (int off = 16; off > 0; off >>= 1) {
        s1 += __shfl_down_sync(0xffffffffu, s1, off);
        s2 += __shfl_down_sync(0xffffffffu, s2, off);
    }
    if (lane == 0) { red1[wp] = s1; red2[wp] = s2; }
    __syncthreads();
    if (f == 0) {
        float t1 = 0.0f, t2 = 0.0f;
        #pragma unroll
        for (int i = 0; i < 16; i++) { t1 += red1[i]; t2 += red2[i]; }
        bc[0] = t1; bc[1] = t2;
    }
    __syncthreads();
    float tot = bc[0], totsq = bc[1];

    float mean = tot * (1.0f / FF);
    float var  = totsq - tot * tot * (1.0f / FF);
    float l2   = sqrtf(fmaxf(var, 0.0f));
    float denom = l2 * 0.04419417382415922f + 1e-5f;     // * F^{-1/2}
    float cell = (val - mean) / denom * 0.7071067811865476f;  // * L^{-1/2}

    float an = 0.99f * g_a[base + f] + 0.01f * cell;
    g_a[base + f] = an;
    g_b[base + f] += an;
}

// ---------------- streams = concat([a, b], channel) ----------------------
__global__ void concat_kernel() {
    int idx = blockIdx.x * 256 + threadIdx.x;
    if (idx >= BB*SS*2*FF) return;
    int bs = idx / (2*FF);
    int j  = idx - bs * (2*FF);
    g_str[idx] = (j < FF) ? g_a[(size_t)bs*FF + j]
                          : g_b[(size_t)bs*FF + (j - FF)];
}

// ---------------- log_softmax over C + NLL gather ------------------------
__global__ void nll_kernel(const int* __restrict__ tgt) {
    int row = blockIdx.x * 8 + (threadIdx.x >> 5);
    int lane = threadIdx.x & 31;
    if (row >= BB*SS) return;
    const float* lr = g_logits + (size_t)row * CC;

    float vals[8];
    float vmax = -1e30f;
    #pragma unroll
    for (int k = 0; k < 8; k++) {
        vals[k] = lr[lane + 32*k];
        vmax = fmaxf(vmax, vals[k]);
    }
    #pragma unroll
    for (int off = 16; off > 0; off >>= 1)
        vmax = fmaxf(vmax, __shfl_xor_sync(0xffffffffu, vmax, off));

    float se = 0.0f;
    #pragma unroll
    for (int k = 0; k < 8; k++) se += expf(vals[k] - vmax);
    #pragma unroll
    for (int off = 16; off > 0; off >>= 1)
        se += __shfl_xor_sync(0xffffffffu, se, off);

    float logZ = vmax + logf(se);
    if (lane == 0) g_nll[row] = logZ - lr[tgt[row]];
}

// ---------------- deterministic final mean -------------------------------
__global__ void reduce_kernel(float* __restrict__ out) {
    __shared__ float sm[256];
    float acc = 0.0f;
    for (int i = threadIdx.x; i < BB*SS; i += 256) acc += g_nll[i];
    sm[threadIdx.x] = acc;
    __syncthreads();
    for (int st = 128; st > 0; st >>= 1) {
        if (threadIdx.x < st) sm[threadIdx.x] += sm[threadIdx.x + st];
        __syncthreads();
    }
    if (threadIdx.x == 0) out[0] = sm[0] / (float)(BB*SS);
}

// ---------------- launcher ----------------------------------------------
extern "C" void kernel_launch(void* const* d_in, const int* in_sizes, int n_in,
                              void* d_out, int out_size) {
    const int*   inp   = (const int*)  d_in[0];
    const int*   tgt   = (const int*)  d_in[1];
    const float* emb   = (const float*)d_in[2];
    const float* w0s   = (const float*)d_in[3];   // (L,3,I,F,1)
    const float* w1s   = (const float*)d_in[4];   // (L,3,I,I,3)
    const float* w2s   = (const float*)d_in[5];   // (L,3,F,I,1)
    const float* out_w = (const float*)d_in[6];   // (C,2F,1)
    const float* out_b = (const float*)d_in[7];   // (C,)
    float* out = (float*)d_out;

    float *ph, *pt1, *pt2, *pd, *psc, *psh, *pstr, *plog;
    float *pw0t, *pw1t, *pw2t;
    cudaGetSymbolAddress((void**)&ph,   g_h);
    cudaGetSymbolAddress((void**)&pt1,  g_t1);
    cudaGetSymbolAddress((void**)&pt2,  g_t2);
    cudaGetSymbolAddress((void**)&pd,   g_d);
    cudaGetSymbolAddress((void**)&psc,  g_sc);
    cudaGetSymbolAddress((void**)&psh,  g_sh);
    cudaGetSymbolAddress((void**)&pstr, g_str);
    cudaGetSymbolAddress((void**)&plog, g_logits);
    cudaGetSymbolAddress((void**)&pw0t, g_w0t);
    cudaGetSymbolAddress((void**)&pw1t, g_w1t);
    cudaGetSymbolAddress((void**)&pw2t, g_w2t);

    // pre-transpose all conv weights (o-fastest layout)
    const long n0 = (long)II * FF;          // per (l,j) w0
    const long n1 = (long)II * II * 3;      // per (l,j) w1
    const long n2 = (long)FF * II;          // per (l,j) w2
    for (int lj = 0; lj < 6; lj++) {
        transpose_w<<<(int)((n0 + 255)/256), 256>>>(w0s + lj*n0, pw0t + lj*n0, II, FF, 1);
        transpose_w<<<(int)((n1 + 255)/256), 256>>>(w1s + lj*n1, pw1t + lj*n1, II, II, 3);
        transpose_w<<<(int)((n2 + 255)/256), 256>>>(w2s + lj*n2, pw2t + lj*n2, FF, II, 1);
    }

    embed_kernel<<<(BB*SS*2*FF + 255)/256, 256>>>(inp, emb);

    float* dests[3] = {pd, psc, psh};
    for (int l = 0; l < 2; l++) {
        h_kernel<<<(BB*SS*FF + 255)/256, 256>>>();
        for (int j = 0; j < 3; j++) {
            int lj = l*3 + j;
            conv_gemm128<FF, II, 1, true>
                <<<dim3(SS/128, II/128, BB), 256>>>(ph,  pw0t + lj*n0, pt1);
            conv_gemm128<II, II, 3, true>
                <<<dim3(SS/128, II/128, BB), 256>>>(pt1, pw1t + lj*n1, pt2);
            conv_gemm128<II, FF, 1, false>
                <<<dim3(SS/128, FF/128, BB), 256>>>(pt2, pw2t + lj*n2, dests[j]);
        }
        cell_kernel<<<BB*SS, FF>>>();
    }

    concat_kernel<<<(BB*SS*2*FF + 255)/256, 256>>>();
    conv_gemm<2*FF, CC, 1, false, true>
        <<<dim3(SS/64, CC/64, BB), 256>>>(pstr, out_w, out_b, plog);

    nll_kernel<<<(BB*SS)/8, 256>>>(tgt);
    reduce_kernel<<<1, 256>>>(out);
}

// round 9
// speedup vs baseline: 3.6428x; 2.3902x over previous
#include <cuda_runtime.h>
#include <math.h>
#include <stdint.h>

// Problem constants
#define BB 2
#define SS 2048
#define FF 512
#define II 1024
#define CC 256

// ---------------- scratch (device globals; no allocation allowed) ----------
__device__ float g_a[BB*SS*FF];
__device__ float g_b[BB*SS*FF];
__device__ float g_h[BB*SS*FF];
__device__ float g_t1[BB*SS*II];
__device__ float g_t2[BB*SS*II];
__device__ float g_d[BB*SS*FF];
__device__ float g_sc[BB*SS*FF];
__device__ float g_sh[BB*SS*FF];
__device__ float g_str[BB*SS*2*FF];
__device__ float g_logits[BB*SS*CC];
__device__ float g_nll[BB*SS];

// transposed weights: Wt[kk*CIN + c][o]  (row-major (R, COUT))
__device__ float g_w0t[2*3*II*FF];        // 6 * 524288
__device__ float g_w1t[2*3*II*II*3];      // 6 * 3145728
__device__ float g_w2t[2*3*FF*II];        // 6 * 524288

// ---------------- weight transpose: Wt[(kk*CIN+c)*COUT+o] = W[(o*CIN+c)*KW+kk]
__global__ void transpose_w(const float* __restrict__ w, float* __restrict__ wt,
                            int COUT, int CIN, int KW) {
    long idx = (long)blockIdx.x * 256 + threadIdx.x;
    long total = (long)COUT * CIN * KW;
    if (idx >= total) return;
    int o = (int)(idx % COUT);
    long rc = idx / COUT;
    int c = (int)(rc % CIN);
    int kk = (int)(rc / CIN);
    wt[idx] = w[((long)o * CIN + c) * KW + kk];
}

// ---------------- embedding gather ---------------------------------------
__global__ void embed_kernel(const int* __restrict__ inp,
                             const float* __restrict__ emb) {
    int idx = blockIdx.x * 256 + threadIdx.x;
    if (idx >= BB*SS*2*FF) return;
    int bs = idx / (2*FF);
    int j  = idx - bs * (2*FF);
    int row = inp[bs];
    float v = emb[(size_t)row * (2*FF) + j];
    if (j < FF) g_a[(size_t)bs*FF + j] = v;
    else        g_b[(size_t)bs*FF + (j - FF)] = v;
}

// ---------------- h = b + feature_embd(f) --------------------------------
__global__ void h_kernel() {
    int idx = blockIdx.x * 256 + threadIdx.x;
    if (idx >= BB*SS*FF) return;
    int f = idx & (FF - 1);
    float f1 = (float)(f + 1);
    float additive = ((f + 1) & 1) ? 1.0f : 0.0f;
    float f2 = (f1 - additive) * 0.5f;
    float f3 = f2 * (8.0f / (float)FF) - 3.707301010157416f; // log(C/(2pi))
    float fe = expf(f3) + additive * 3.14159265358979f;
    g_h[idx] = g_b[idx] + fe;
}

// ---------------- tf32 helpers -------------------------------------------
__device__ __forceinline__ uint32_t f2tf32(float f) {
    uint32_t u;
    asm("cvt.rna.tf32.f32 %0, %1;" : "=r"(u) : "f"(f));
    return u;
}

#define CP_ASYNC16(dst_u32, src_ptr, sz)                                      \
    asm volatile("cp.async.ca.shared.global [%0], [%1], 16, %2;"              \
                 :: "r"(dst_u32), "l"(src_ptr), "r"(sz))
#define CP_ASYNC_COMMIT() asm volatile("cp.async.commit_group;")
#define CP_ASYNC_WAIT0()  asm volatile("cp.async.wait_group 0;")

// ---------------- tensor-core conv-GEMM (tf32 mma.sync) ------------------
// y[b,s,o] = act( sum_r Wt[r][o] * x[b, s + r/CIN - (KW-1), r%CIN] )
// Block tile 128(M=s) x 128(N=o) x 16(K). 8 warps: 2(m) x 4(n), warp tile
// 64x32 = 4x4 grid of m16n8k8 per k-step (2 k-steps per slab).
// cp.async double-buffered smem.
// APAD=20: A-frag bank = (20*qid + qlo) mod 32  -> 32 distinct (conflict-free)
// BPAD=136: B-frag bank = (8*qlo + qid) mod 32  -> 32 distinct (conflict-free)
#define APAD 20   // A row stride in floats (128 rows x 16 K + pad)
#define BPAD 136  // B row stride in floats (16 K rows x 128 N + pad)

template<int CIN, int COUT, int KW, bool RELU>
__global__ __launch_bounds__(256, 2)
void conv_mma(const float* __restrict__ x,
              const float* __restrict__ wt,
              float* __restrict__ y) {
    constexpr int R = CIN * KW;
    constexpr int NIT = R / 16;
    const int s0 = blockIdx.x * 128;
    const int o0 = blockIdx.y * 128;
    const int bq = blockIdx.z;
    const float* xb = x + (size_t)bq * SS * CIN;
    float* yb = y + (size_t)bq * SS * COUT;

    __shared__ __align__(16) float As[2][128 * APAD];  // 20480 B
    __shared__ __align__(16) float Bs[2][16 * BPAD];   // 17408 B

    const int tid  = threadIdx.x;
    const int wid  = tid >> 5;
    const int lane = tid & 31;
    const int wm   = wid >> 2;        // 0..1
    const int wn   = wid & 3;         // 0..3
    const int qid  = lane >> 2;       // 0..7
    const int qlo  = lane & 3;        // 0..3

    const uint32_t aBase0 = (uint32_t)__cvta_generic_to_shared(&As[0][0]);
    const uint32_t aBase1 = (uint32_t)__cvta_generic_to_shared(&As[1][0]);
    const uint32_t bBase0 = (uint32_t)__cvta_generic_to_shared(&Bs[0][0]);
    const uint32_t bBase1 = (uint32_t)__cvta_generic_to_shared(&Bs[1][0]);

    float acc[4][4][4];
    #pragma unroll
    for (int mi = 0; mi < 4; mi++)
        #pragma unroll
        for (int ni = 0; ni < 4; ni++)
            #pragma unroll
            for (int r = 0; r < 4; r++) acc[mi][ni][r] = 0.0f;

    // A tile: 128 rows x 4 float4 (16 K) = 512 float4 -> 2 per thread
    // B tile: 16 rows x 32 float4 (128 N) = 512 float4 -> 2 per thread
#define ISSUE_TILE(ITV, AB, BBv) do {                                         \
        int r0_ = (ITV) * 16;                                                 \
        int kk_ = r0_ / CIN;                                                  \
        int c0_ = r0_ - kk_ * CIN;                                            \
        _Pragma("unroll")                                                     \
        for (int u = 0; u < 2; u++) {                                         \
            int idx = tid + u * 256;                                          \
            int m_  = idx >> 2;                                               \
            int c4_ = idx & 3;                                                \
            int ssx_ = s0 + m_ + kk_ - (KW - 1);                              \
            const float* src = (ssx_ >= 0)                                    \
                ? &xb[(size_t)ssx_ * CIN + c0_ + c4_ * 4] : xb;               \
            int sz = (ssx_ >= 0) ? 16 : 0;                                    \
            CP_ASYNC16((AB) + (uint32_t)(m_ * APAD + c4_ * 4) * 4u, src, sz); \
        }                                                                     \
        _Pragma("unroll")                                                     \
        for (int u = 0; u < 2; u++) {                                         \
            int idx = tid + u * 256;                                          \
            int r_  = idx >> 5;                                               \
            int c4_ = idx & 31;                                               \
            const float* src = &wt[(size_t)(r0_ + r_) * COUT + o0 + c4_ * 4]; \
            CP_ASYNC16((BBv) + (uint32_t)(r_ * BPAD + c4_ * 4) * 4u, src, 16);\
        }                                                                     \
        CP_ASYNC_COMMIT();                                                    \
    } while (0)

    ISSUE_TILE(0, aBase0, bBase0);
    CP_ASYNC_WAIT0();
    __syncthreads();

    int buf = 0;
    for (int it = 0; it < NIT; ++it) {
        if (it + 1 < NIT) {
            if (buf == 0) ISSUE_TILE(it + 1, aBase1, bBase1);
            else          ISSUE_TILE(it + 1, aBase0, bBase0);
        }
        const float* A = As[buf];
        const float* B = Bs[buf];
        #pragma unroll
        for (int k0 = 0; k0 < 16; k0 += 8) {
            uint32_t a[4][4];
            #pragma unroll
            for (int mi = 0; mi < 4; mi++) {
                int row = wm * 64 + mi * 16 + qid;
                int col = k0 + qlo;
                a[mi][0] = f2tf32(A[row * APAD + col]);
                a[mi][1] = f2tf32(A[(row + 8) * APAD + col]);
                a[mi][2] = f2tf32(A[row * APAD + col + 4]);
                a[mi][3] = f2tf32(A[(row + 8) * APAD + col + 4]);
            }
            #pragma unroll
            for (int ni = 0; ni < 4; ni++) {
                int brow = k0 + qlo;
                int bcol = wn * 32 + ni * 8 + qid;
                uint32_t b0 = f2tf32(B[brow * BPAD + bcol]);
                uint32_t b1 = f2tf32(B[(brow + 4) * BPAD + bcol]);
                #pragma unroll
                for (int mi = 0; mi < 4; mi++) {
                    asm volatile(
                        "mma.sync.aligned.m16n8k8.row.col.f32.tf32.tf32.f32 "
                        "{%0,%1,%2,%3}, {%4,%5,%6,%7}, {%8,%9}, {%0,%1,%2,%3};"
                        : "+f"(acc[mi][ni][0]), "+f"(acc[mi][ni][1]),
                          "+f"(acc[mi][ni][2]), "+f"(acc[mi][ni][3])
                        : "r"(a[mi][0]), "r"(a[mi][1]), "r"(a[mi][2]), "r"(a[mi][3]),
                          "r"(b0), "r"(b1));
                }
            }
        }
        if (it + 1 < NIT) CP_ASYNC_WAIT0();
        __syncthreads();
        buf ^= 1;
    }
#undef ISSUE_TILE

    // epilogue: c0:(row, 2q) c1:(row, 2q+1) c2:(row+8, 2q) c3:(row+8, 2q+1)
    #pragma unroll
    for (int mi = 0; mi < 4; mi++) {
        int row = s0 + wm * 64 + mi * 16 + qid;
        #pragma unroll
        for (int ni = 0; ni < 4; ni++) {
            int col = o0 + wn * 32 + ni * 8 + 2 * qlo;
            float2 v0, v1;
            v0.x = acc[mi][ni][0]; v0.y = acc[mi][ni][1];
            v1.x = acc[mi][ni][2]; v1.y = acc[mi][ni][3];
            if (RELU) {
                v0.x = fmaxf(v0.x, 0.f); v0.y = fmaxf(v0.y, 0.f);
                v1.x = fmaxf(v1.x, 0.f); v1.y = fmaxf(v1.y, 0.f);
            }
            *(float2*)&yb[(size_t)row * COUT + col]       = v0;
            *(float2*)&yb[(size_t)(row + 8) * COUT + col] = v1;
        }
    }
}

// ---------------- small 64x64 conv-GEMM (final output GEMM) --------------
template<int CIN, int COUT, int KW, bool RELU, bool BIAS>
__global__ void conv_gemm(const float* __restrict__ x,
                          const float* __restrict__ w,
                          const float* __restrict__ bias,
                          float* __restrict__ y) {
    constexpr int R = CIN * KW;
    const int s0 = blockIdx.x * 64;
    const int o0 = blockIdx.y * 64;
    const int bq = blockIdx.z;
    const float* xb = x + (size_t)bq * SS * CIN;
    float* yb = y + (size_t)bq * SS * COUT;

    __shared__ float Xs[64][17];
    __shared__ float Ws[64][17];

    const int tid = threadIdx.x;
    const int tx = tid & 15;
    const int ty = tid >> 4;

    float acc[4][4];
    #pragma unroll
    for (int i = 0; i < 4; i++)
        #pragma unroll
        for (int j = 0; j < 4; j++) acc[i][j] = 0.0f;

    for (int r0 = 0; r0 < R; r0 += 16) {
        #pragma unroll
        for (int u = 0; u < 4; u++) {
            int idx = tid + u * 256;
            int ri = idx & 15;
            int m  = idx >> 4;
            int rr = r0 + ri;
            int kk = rr / CIN;
            int c  = rr - kk * CIN;
            int ss = s0 + m + kk - (KW - 1);
            Xs[m][ri] = (ss >= 0) ? xb[(size_t)ss * CIN + c] : 0.0f;
            Ws[m][ri] = w[(size_t)(o0 + m) * R + (size_t)c * KW + kk];
        }
        __syncthreads();
        #pragma unroll
        for (int r = 0; r < 16; r++) {
            float av[4], bv[4];
            #pragma unroll
            for (int i = 0; i < 4; i++) av[i] = Ws[tx + 16*i][r];
            #pragma unroll
            for (int j = 0; j < 4; j++) bv[j] = Xs[ty + 16*j][r];
            #pragma unroll
            for (int i = 0; i < 4; i++)
                #pragma unroll
                for (int j = 0; j < 4; j++)
                    acc[i][j] = fmaf(av[i], bv[j], acc[i][j]);
        }
        __syncthreads();
    }

    #pragma unroll
    for (int j = 0; j < 4; j++) {
        int sI = s0 + ty + 16*j;
        #pragma unroll
        for (int i = 0; i < 4; i++) {
            int o = o0 + tx + 16*i;
            float v = acc[i][j];
            if (BIAS) v += bias[o];
            if (RELU) v = fmaxf(v, 0.0f);
            yb[(size_t)sI * COUT + o] = v;
        }
    }
}

// ---------------- cell update: cumsum over channels, norm, EMA -----------
__global__ void cell_kernel() {
    int bs = blockIdx.x;
    int s  = bs & (SS - 1);
    int f  = threadIdx.x;
    size_t base = (size_t)bs * FF;

    float v = g_d[base + f];

    int lane = f & 31, wp = f >> 5;
    #pragma unroll
    for (int off = 1; off < 32; off <<= 1) {
        float n = __shfl_up_sync(0xffffffffu, v, off);
        if (lane >= off) v += n;
    }
    __shared__ float wsum[16];
    __shared__ float red1[16], red2[16];
    __shared__ float bc[2];
    if (lane == 31) wsum[wp] = v;
    __syncthreads();
    if (f < 16) {
        float t = wsum[f];
        #pragma unroll
        for (int off = 1; off < 16; off <<= 1) {
            float n = __shfl_up_sync(0x0000ffffu, t, off);
            if (f >= off) t += n;
        }
        wsum[f] = t;
    }
    __syncthreads();
    float cum = v + (wp > 0 ? wsum[wp - 1] : 0.0f);

    float val = cum / (float)(s + 1) * g_sc[base + f] + g_sh[base + f];

    float s1 = val, s2 = val * val;
    #pragma unroll
    for (int off = 16; off > 0; off >>= 1) {
        s1 += __shfl_down_sync(0xffffffffu, s1, off);
        s2 += __shfl_down_sync(0xffffffffu, s2, off);
    }
    if (lane == 0) { red1[wp] = s1; red2[wp] = s2; }
    __syncthreads();
    if (f == 0) {
        float t1 = 0.0f, t2 = 0.0f;
        #pragma unroll
        for (int i = 0; i < 16; i++) { t1 += red1[i]; t2 += red2[i]; }
        bc[0] = t1; bc[1] = t2;
    }
    __syncthreads();
    float tot = bc[0], totsq = bc[1];

    float mean = tot * (1.0f / FF);
    float var  = totsq - tot * tot * (1.0f / FF);
    float l2   = sqrtf(fmaxf(var, 0.0f));
    float denom = l2 * 0.04419417382415922f + 1e-5f;     // * F^{-1/2}
    float cell = (val - mean) / denom * 0.7071067811865476f;  // * L^{-1/2}

    float an = 0.99f * g_a[base + f] + 0.01f * cell;
    g_a[base + f] = an;
    g_b[base + f] += an;
}

// ---------------- streams = concat([a, b], channel) ----------------------
__global__ void concat_kernel() {
    int idx = blockIdx.x * 256 + threadIdx.x;
    if (idx >= BB*SS*2*FF) return;
    int bs = idx / (2*FF);
    int j  = idx - bs * (2*FF);
    g_str[idx] = (j < FF) ? g_a[(size_t)bs*FF + j]
                          : g_b[(size_t)bs*FF + (j - FF)];
}

// ---------------- log_softmax over C + NLL gather ------------------------
__global__ void nll_kernel(const int* __restrict__ tgt) {
    int row = blockIdx.x * 8 + (threadIdx.x >> 5);
    int lane = threadIdx.x & 31;
    if (row >= BB*SS) return;
    const float* lr = g_logits + (size_t)row * CC;

    float vals[8];
    float vmax = -1e30f;
    #pragma unroll
    for (int k = 0; k < 8; k++) {
        vals[k] = lr[lane + 32*k];
        vmax = fmaxf(vmax, vals[k]);
    }
    #pragma unroll
    for (int off = 16; off > 0; off >>= 1)
        vmax = fmaxf(vmax, __shfl_xor_sync(0xffffffffu, vmax, off));

    float se = 0.0f;
    #pragma unroll
    for (int k = 0; k < 8; k++) se += expf(vals[k] - vmax);
    #pragma unroll
    for (int off = 16; off > 0; off >>= 1)
        se += __shfl_xor_sync(0xffffffffu, se, off);

    float logZ = vmax + logf(se);
    if (lane == 0) g_nll[row] = logZ - lr[tgt[row]];
}

// ---------------- deterministic final mean -------------------------------
__global__ void reduce_kernel(float* __restrict__ out) {
    __shared__ float sm[256];
    float acc = 0.0f;
    for (int i = threadIdx.x; i < BB*SS; i += 256) acc += g_nll[i];
    sm[threadIdx.x] = acc;
    __syncthreads();
    for (int st = 128; st > 0; st >>= 1) {
        if (threadIdx.x < st) sm[threadIdx.x] += sm[threadIdx.x + st];
        __syncthreads();
    }
    if (threadIdx.x == 0) out[0] = sm[0] / (float)(BB*SS);
}

// ---------------- launcher ----------------------------------------------
extern "C" void kernel_launch(void* const* d_in, const int* in_sizes, int n_in,
                              void* d_out, int out_size) {
    const int*   inp   = (const int*)  d_in[0];
    const int*   tgt   = (const int*)  d_in[1];
    const float* emb   = (const float*)d_in[2];
    const float* w0s   = (const float*)d_in[3];   // (L,3,I,F,1)
    const float* w1s   = (const float*)d_in[4];   // (L,3,I,I,3)
    const float* w2s   = (const float*)d_in[5];   // (L,3,F,I,1)
    const float* out_w = (const float*)d_in[6];   // (C,2F,1)
    const float* out_b = (const float*)d_in[7];   // (C,)
    float* out = (float*)d_out;

    float *ph, *pt1, *pt2, *pd, *psc, *psh, *pstr, *plog;
    float *pw0t, *pw1t, *pw2t;
    cudaGetSymbolAddress((void**)&ph,   g_h);
    cudaGetSymbolAddress((void**)&pt1,  g_t1);
    cudaGetSymbolAddress((void**)&pt2,  g_t2);
    cudaGetSymbolAddress((void**)&pd,   g_d);
    cudaGetSymbolAddress((void**)&psc,  g_sc);
    cudaGetSymbolAddress((void**)&psh,  g_sh);
    cudaGetSymbolAddress((void**)&pstr, g_str);
    cudaGetSymbolAddress((void**)&plog, g_logits);
    cudaGetSymbolAddress((void**)&pw0t, g_w0t);
    cudaGetSymbolAddress((void**)&pw1t, g_w1t);
    cudaGetSymbolAddress((void**)&pw2t, g_w2t);

    // pre-transpose all conv weights (o-fastest layout)
    const long n0 = (long)II * FF;          // per (l,j) w0
    const long n1 = (long)II * II * 3;      // per (l,j) w1
    const long n2 = (long)FF * II;          // per (l,j) w2
    for (int lj = 0; lj < 6; lj++) {
        transpose_w<<<(int)((n0 + 255)/256), 256>>>(w0s + lj*n0, pw0t + lj*n0, II, FF, 1);
        transpose_w<<<(int)((n1 + 255)/256), 256>>>(w1s + lj*n1, pw1t + lj*n1, II, II, 3);
        transpose_w<<<(int)((n2 + 255)/256), 256>>>(w2s + lj*n2, pw2t + lj*n2, FF, II, 1);
    }

    embed_kernel<<<(BB*SS*2*FF + 255)/256, 256>>>(inp, emb);

    float* dests[3] = {pd, psc, psh};
    for (int l = 0; l < 2; l++) {
        h_kernel<<<(BB*SS*FF + 255)/256, 256>>>();
        for (int j = 0; j < 3; j++) {
            int lj = l*3 + j;
            conv_mma<FF, II, 1, true>
                <<<dim3(SS/128, II/128, BB), 256>>>(ph,  pw0t + lj*n0, pt1);
            conv_mma<II, II, 3, true>
                <<<dim3(SS/128, II/128, BB), 256>>>(pt1, pw1t + lj*n1, pt2);
            conv_mma<II, FF, 1, false>
                <<<dim3(SS/128, FF/128, BB), 256>>>(pt2, pw2t + lj*n2, dests[j]);
        }
        cell_kernel<<<BB*SS, FF>>>();
    }

    concat_kernel<<<(BB*SS*2*FF + 255)/256, 256>>>();
    conv_gemm<2*FF, CC, 1, false, true>
        <<<dim3(SS/64, CC/64, BB), 256>>>(pstr, out_w, out_b, plog);

    nll_kernel<<<(BB*SS)/8, 256>>>(tgt);
    reduce_kernel<<<1, 256>>>(out);
}

// round 15
// speedup vs baseline: 4.0656x; 1.1161x over previous
#include <cuda_runtime.h>
#include <math.h>
#include <stdint.h>

// Problem constants
#define BB 2
#define SS 2048
#define FF 512
#define II 1024
#define CC 256

// ---------------- scratch (device globals; no allocation allowed) ----------
__device__ float g_a[BB*SS*FF];
__device__ float g_b[BB*SS*FF];
__device__ float g_h[BB*SS*FF];
__device__ float g_t1[3*BB*SS*II];       // per-branch j=0..2
__device__ float g_t2[3*BB*SS*II];
__device__ float g_dsh[3*BB*SS*FF];      // j=0: d, j=1: sc, j=2: sh
__device__ float g_str[BB*SS*2*FF];
__device__ float g_logits[BB*SS*CC];
__device__ float g_nll[BB*SS];

// transposed weights: per (l,j): Wt[kk*CIN + c][o]  (row-major (R, COUT))
__device__ float g_w0t[2*3*II*FF];        // 6 * 524288
__device__ float g_w1t[2*3*II*II*3];      // 6 * 3145728
__device__ float g_w2t[2*3*FF*II];        // 6 * 524288

// ---------------- batched weight transpose --------------------------------
// For each of nb blocks: Wt[(kk*CIN+c)*COUT+o] = W[(o*CIN+c)*KW+kk]
__global__ void transpose_w_b(const float* __restrict__ w, float* __restrict__ wt,
                              int COUT, int CIN, int KW, int nb) {
    long idx = (long)blockIdx.x * 256 + threadIdx.x;
    long per = (long)COUT * CIN * KW;
    if (idx >= per * nb) return;
    int bN = (int)(idx / per);
    long r = idx - (long)bN * per;
    int o = (int)(r % COUT);
    long rc = r / COUT;
    int c = (int)(rc % CIN);
    int kk = (int)(rc / CIN);
    wt[idx] = w[(long)bN * per + ((long)o * CIN + c) * KW + kk];
}

// ---------------- embedding gather ---------------------------------------
__global__ void embed_kernel(const int* __restrict__ inp,
                             const float* __restrict__ emb) {
    int idx = blockIdx.x * 256 + threadIdx.x;
    if (idx >= BB*SS*2*FF) return;
    int bs = idx / (2*FF);
    int j  = idx - bs * (2*FF);
    int row = inp[bs];
    float v = emb[(size_t)row * (2*FF) + j];
    if (j < FF) g_a[(size_t)bs*FF + j] = v;
    else        g_b[(size_t)bs*FF + (j - FF)] = v;
}

// ---------------- h = b + feature_embd(f) --------------------------------
__global__ void h_kernel() {
    int idx = blockIdx.x * 256 + threadIdx.x;
    if (idx >= BB*SS*FF) return;
    int f = idx & (FF - 1);
    float f1 = (float)(f + 1);
    float additive = ((f + 1) & 1) ? 1.0f : 0.0f;
    float f2 = (f1 - additive) * 0.5f;
    float f3 = f2 * (8.0f / (float)FF) - 3.707301010157416f; // log(C/(2pi))
    float fe = expf(f3) + additive * 3.14159265358979f;
    g_h[idx] = g_b[idx] + fe;
}

// ---------------- tf32 helpers -------------------------------------------
__device__ __forceinline__ uint32_t f2tf32(float f) {
    uint32_t u;
    asm("cvt.rna.tf32.f32 %0, %1;" : "=r"(u) : "f"(f));
    return u;
}

#define CP_ASYNC16(dst_u32, src_ptr, sz)                                      \
    asm volatile("cp.async.ca.shared.global [%0], [%1], 16, %2;"              \
                 :: "r"(dst_u32), "l"(src_ptr), "r"(sz))
#define CP_ASYNC_COMMIT() asm volatile("cp.async.commit_group;")
#define CP_ASYNC_WAIT0()  asm volatile("cp.async.wait_group 0;")

// ---------------- tensor-core conv-GEMM (tf32 mma.sync) ------------------
// Branch-batched: blockIdx.z encodes (j, bq): bq = z&1, j = z>>1.
// y[j][b,s,o] = act( sum_r Wt[j][r][o] * x[j][b, s + r/CIN - (KW-1), r%CIN] )
// Block tile 128(M=s) x 128(N=o) x 16(K). 8 warps: 2(m) x 4(n), warp tile
// 64x32 = 4x4 grid of m16n8k8 per k-step (2 k-steps per slab).
// cp.async double-buffered smem.
// APAD=20: A-frag bank = (20*qid + qlo) mod 32  -> 32 distinct (conflict-free)
// BPAD=136: B-frag bank = (8*qlo + qid) mod 32  -> 32 distinct (conflict-free)
#define APAD 20   // A row stride in floats (128 rows x 16 K + pad)
#define BPAD 136  // B row stride in floats (16 K rows x 128 N + pad)

template<int CIN, int COUT, int KW, bool RELU>
__global__ __launch_bounds__(256, 2)
void conv_mma(const float* __restrict__ x, size_t xjs,
              const float* __restrict__ wt, size_t wjs,
              float* __restrict__ y, size_t yjs) {
    constexpr int R = CIN * KW;
    constexpr int NIT = R / 16;
    const int s0 = blockIdx.x * 128;
    const int o0 = blockIdx.y * 128;
    const int bq = blockIdx.z & 1;
    const int jb = blockIdx.z >> 1;
    const float* xb = x + (size_t)jb * xjs + (size_t)bq * SS * CIN;
    const float* wtb = wt + (size_t)jb * wjs;
    float* yb = y + (size_t)jb * yjs + (size_t)bq * SS * COUT;

    __shared__ __align__(16) float As[2][128 * APAD];  // 20480 B
    __shared__ __align__(16) float Bs[2][16 * BPAD];   // 17408 B

    const int tid  = threadIdx.x;
    const int wid  = tid >> 5;
    const int lane = tid & 31;
    const int wm   = wid >> 2;        // 0..1
    const int wn   = wid & 3;         // 0..3
    const int qid  = lane >> 2;       // 0..7
    const int qlo  = lane & 3;        // 0..3

    const uint32_t aBase0 = (uint32_t)__cvta_generic_to_shared(&As[0][0]);
    const uint32_t aBase1 = (uint32_t)__cvta_generic_to_shared(&As[1][0]);
    const uint32_t bBase0 = (uint32_t)__cvta_generic_to_shared(&Bs[0][0]);
    const uint32_t bBase1 = (uint32_t)__cvta_generic_to_shared(&Bs[1][0]);

    float acc[4][4][4];
    #pragma unroll
    for (int mi = 0; mi < 4; mi++)
        #pragma unroll
        for (int ni = 0; ni < 4; ni++)
            #pragma unroll
            for (int r = 0; r < 4; r++) acc[mi][ni][r] = 0.0f;

    // A tile: 128 rows x 4 float4 (16 K) = 512 float4 -> 2 per thread
    // B tile: 16 rows x 32 float4 (128 N) = 512 float4 -> 2 per thread
#define ISSUE_TILE(ITV, AB, BBv) do {                                         \
        int r0_ = (ITV) * 16;                                                 \
        int kk_ = r0_ / CIN;                                                  \
        int c0_ = r0_ - kk_ * CIN;                                            \
        _Pragma("unroll")                                                     \
        for (int u = 0; u < 2; u++) {                                         \
            int idx = tid + u * 256;                                          \
            int m_  = idx >> 2;                                               \
            int c4_ = idx & 3;                                                \
            int ssx_ = s0 + m_ + kk_ - (KW - 1);                              \
            const float* src = (ssx_ >= 0)                                    \
                ? &xb[(size_t)ssx_ * CIN + c0_ + c4_ * 4] : xb;               \
            int sz = (ssx_ >= 0) ? 16 : 0;                                    \
            CP_ASYNC16((AB) + (uint32_t)(m_ * APAD + c4_ * 4) * 4u, src, sz); \
        }                                                                     \
        _Pragma("unroll")                                                     \
        for (int u = 0; u < 2; u++) {                                         \
            int idx = tid + u * 256;                                          \
            int r_  = idx >> 5;                                               \
            int c4_ = idx & 31;                                               \
            const float* src = &wtb[(size_t)(r0_ + r_) * COUT + o0 + c4_ * 4];\
            CP_ASYNC16((BBv) + (uint32_t)(r_ * BPAD + c4_ * 4) * 4u, src, 16);\
        }                                                                     \
        CP_ASYNC_COMMIT();                                                    \
    } while (0)

    ISSUE_TILE(0, aBase0, bBase0);
    CP_ASYNC_WAIT0();
    __syncthreads();

    int buf = 0;
    for (int it = 0; it < NIT; ++it) {
        if (it + 1 < NIT) {
            if (buf == 0) ISSUE_TILE(it + 1, aBase1, bBase1);
            else          ISSUE_TILE(it + 1, aBase0, bBase0);
        }
        const float* A = As[buf];
        const float* B = Bs[buf];
        #pragma unroll
        for (int k0 = 0; k0 < 16; k0 += 8) {
            uint32_t a[4][4];
            #pragma unroll
            for (int mi = 0; mi < 4; mi++) {
                int row = wm * 64 + mi * 16 + qid;
                int col = k0 + qlo;
                a[mi][0] = f2tf32(A[row * APAD + col]);
                a[mi][1] = f2tf32(A[(row + 8) * APAD + col]);
                a[mi][2] = f2tf32(A[row * APAD + col + 4]);
                a[mi][3] = f2tf32(A[(row + 8) * APAD + col + 4]);
            }
            #pragma unroll
            for (int ni = 0; ni < 4; ni++) {
                int brow = k0 + qlo;
                int bcol = wn * 32 + ni * 8 + qid;
                uint32_t b0 = f2tf32(B[brow * BPAD + bcol]);
                uint32_t b1 = f2tf32(B[(brow + 4) * BPAD + bcol]);
                #pragma unroll
                for (int mi = 0; mi < 4; mi++) {
                    asm volatile(
                        "mma.sync.aligned.m16n8k8.row.col.f32.tf32.tf32.f32 "
                        "{%0,%1,%2,%3}, {%4,%5,%6,%7}, {%8,%9}, {%0,%1,%2,%3};"
                        : "+f"(acc[mi][ni][0]), "+f"(acc[mi][ni][1]),
                          "+f"(acc[mi][ni][2]), "+f"(acc[mi][ni][3])
                        : "r"(a[mi][0]), "r"(a[mi][1]), "r"(a[mi][2]), "r"(a[mi][3]),
                          "r"(b0), "r"(b1));
                }
            }
        }
        if (it + 1 < NIT) CP_ASYNC_WAIT0();
        __syncthreads();
        buf ^= 1;
    }
#undef ISSUE_TILE

    // epilogue: c0:(row, 2q) c1:(row, 2q+1) c2:(row+8, 2q) c3:(row+8, 2q+1)
    #pragma unroll
    for (int mi = 0; mi < 4; mi++) {
        int row = s0 + wm * 64 + mi * 16 + qid;
        #pragma unroll
        for (int ni = 0; ni < 4; ni++) {
            int col = o0 + wn * 32 + ni * 8 + 2 * qlo;
            float2 v0, v1;
            v0.x = acc[mi][ni][0]; v0.y = acc[mi][ni][1];
            v1.x = acc[mi][ni][2]; v1.y = acc[mi][ni][3];
            if (RELU) {
                v0.x = fmaxf(v0.x, 0.f); v0.y = fmaxf(v0.y, 0.f);
                v1.x = fmaxf(v1.x, 0.f); v1.y = fmaxf(v1.y, 0.f);
            }
            *(float2*)&yb[(size_t)row * COUT + col]       = v0;
            *(float2*)&yb[(size_t)(row + 8) * COUT + col] = v1;
        }
    }
}

// ---------------- small 64x64 conv-GEMM (final output GEMM) --------------
template<int CIN, int COUT, int KW, bool RELU, bool BIAS>
__global__ void conv_gemm(const float* __restrict__ x,
                          const float* __restrict__ w,
                          const float* __restrict__ bias,
                          float* __restrict__ y) {
    constexpr int R = CIN * KW;
    const int s0 = blockIdx.x * 64;
    const int o0 = blockIdx.y * 64;
    const int bq = blockIdx.z;
    const float* xb = x + (size_t)bq * SS * CIN;
    float* yb = y + (size_t)bq * SS * COUT;

    __shared__ float Xs[64][17];
    __shared__ float Ws[64][17];

    const int tid = threadIdx.x;
    const int tx = tid & 15;
    const int ty = tid >> 4;

    float acc[4][4];
    #pragma unroll
    for (int i = 0; i < 4; i++)
        #pragma unroll
        for (int j = 0; j < 4; j++) acc[i][j] = 0.0f;

    for (int r0 = 0; r0 < R; r0 += 16) {
        #pragma unroll
        for (int u = 0; u < 4; u++) {
            int idx = tid + u * 256;
            int ri = idx & 15;
            int m  = idx >> 4;
            int rr = r0 + ri;
            int kk = rr / CIN;
            int c  = rr - kk * CIN;
            int ss = s0 + m + kk - (KW - 1);
            Xs[m][ri] = (ss >= 0) ? xb[(size_t)ss * CIN + c] : 0.0f;
            Ws[m][ri] = w[(size_t)(o0 + m) * R + (size_t)c * KW + kk];
        }
        __syncthreads();
        #pragma unroll
        for (int r = 0; r < 16; r++) {
            float av[4], bv[4];
            #pragma unroll
            for (int i = 0; i < 4; i++) av[i] = Ws[tx + 16*i][r];
            #pragma unroll
            for (int j = 0; j < 4; j++) bv[j] = Xs[ty + 16*j][r];
            #pragma unroll
            for (int i = 0; i < 4; i++)
                #pragma unroll
                for (int j = 0; j < 4; j++)
                    acc[i][j] = fmaf(av[i], bv[j], acc[i][j]);
        }
        __syncthreads();
    }

    #pragma unroll
    for (int j = 0; j < 4; j++) {
        int sI = s0 + ty + 16*j;
        #pragma unroll
        for (int i = 0; i < 4; i++) {
            int o = o0 + tx + 16*i;
            float v = acc[i][j];
            if (BIAS) v += bias[o];
            if (RELU) v = fmaxf(v, 0.0f);
            yb[(size_t)sI * COUT + o] = v;
        }
    }
}

// ---------------- cell update: cumsum over channels, norm, EMA -----------
__global__ void cell_kernel() {
    int bs = blockIdx.x;
    int s  = bs & (SS - 1);
    int f  = threadIdx.x;
    size_t base = (size_t)bs * FF;
    const size_t NFa = (size_t)BB * SS * FF;

    float v = g_dsh[base + f];                 // d

    int lane = f & 31, wp = f >> 5;
    #pragma unroll
    for (int off = 1; off < 32; off <<= 1) {
        float n = __shfl_up_sync(0xffffffffu, v, off);
        if (lane >= off) v += n;
    }
    __shared__ float wsum[16];
    __shared__ float red1[16], red2[16];
    __shared__ float bc[2];
    if (lane == 31) wsum[wp] = v;
    __syncthreads();
    if (f < 16) {
        float t = wsum[f];
        #pragma unroll
        for (int off = 1; off < 16; off <<= 1) {
            float n = __shfl_up_sync(0x0000ffffu, t, off);
            if (f >= off) t += n;
        }
        wsum[f] = t;
    }
    __syncthreads();
    float cum = v + (wp > 0 ? wsum[wp - 1] : 0.0f);

    float val = cum / (float)(s + 1) * g_dsh[NFa + base + f]     // * sc
              + g_dsh[2*NFa + base + f];                          // + sh

    float s1 = val, s2 = val * val;
    #pragma unroll
    for (int off = 16; off > 0; off >>= 1) {
        s1 += __shfl_down_sync(0xffffffffu, s1, off);
        s2 += __shfl_down_sync(0xffffffffu, s2, off);
    }
    if (lane == 0) { red1[wp] = s1; red2[wp] = s2; }
    __syncthreads();
    if (f == 0) {
        float t1 = 0.0f, t2 = 0.0f;
        #pragma unroll
        for (int i = 0; i < 16; i++) { t1 += red1[i]; t2 += red2[i]; }
        bc[0] = t1; bc[1] = t2;
    }
    __syncthreads();
    float tot = bc[0], totsq = bc[1];

    float mean = tot * (1.0f / FF);
    float var  = totsq - tot * tot * (1.0f / FF);
    float l2   = sqrtf(fmaxf(var, 0.0f));
    float denom = l2 * 0.04419417382415922f + 1e-5f;     // * F^{-1/2}
    float cell = (val - mean) / denom * 0.7071067811865476f;  // * L^{-1/2}

    float an = 0.99f * g_a[base + f] + 0.01f * cell;
    g_a[base + f] = an;
    g_b[base + f] += an;
}

// ---------------- streams = concat([a, b], channel) ----------------------
__global__ void concat_kernel() {
    int idx = blockIdx.x * 256 + threadIdx.x;
    if (idx >= BB*SS*2*FF) return;
    int bs = idx / (2*FF);
    int j  = idx - bs * (2*FF);
    g_str[idx] = (j < FF) ? g_a[(size_t)bs*FF + j]
                          : g_b[(size_t)bs*FF + (j - FF)];
}

// ---------------- log_softmax over C + NLL gather ------------------------
__global__ void nll_kernel(const int* __restrict__ tgt) {
    int row = blockIdx.x * 8 + (threadIdx.x >> 5);
    int lane = threadIdx.x & 31;
    if (row >= BB*SS) return;
    const float* lr = g_logits + (size_t)row * CC;

    float vals[8];
    float vmax = -1e30f;
    #pragma unroll
    for (int k = 0; k < 8; k++) {
        vals[k] = lr[lane + 32*k];
        vmax = fmaxf(vmax, vals[k]);
    }
    #pragma unroll
    for (int off = 16; off > 0; off >>= 1)
        vmax = fmaxf(vmax, __shfl_xor_sync(0xffffffffu, vmax, off));

    float se = 0.0f;
    #pragma unroll
    for (int k = 0; k < 8; k++) se += expf(vals[k] - vmax);
    #pragma unroll
    for (int off = 16; off > 0; off >>= 1)
        se += __shfl_xor_sync(0xffffffffu, se, off);

    float logZ = vmax + logf(se);
    if (lane == 0) g_nll[row] = logZ - lr[tgt[row]];
}

// ---------------- deterministic final mean -------------------------------
__global__ void reduce_kernel(float* __restrict__ out) {
    __shared__ float sm[256];
    float acc = 0.0f;
    for (int i = threadIdx.x; i < BB*SS; i += 256) acc += g_nll[i];
    sm[threadIdx.x] = acc;
    __syncthreads();
    for (int st = 128; st > 0; st >>= 1) {
        if (threadIdx.x < st) sm[threadIdx.x] += sm[threadIdx.x + st];
        __syncthreads();
    }
    if (threadIdx.x == 0) out[0] = sm[0] / (float)(BB*SS);
}

// ---------------- launcher ----------------------------------------------
extern "C" void kernel_launch(void* const* d_in, const int* in_sizes, int n_in,
                              void* d_out, int out_size) {
    const int*   inp   = (const int*)  d_in[0];
    const int*   tgt   = (const int*)  d_in[1];
    const float* emb   = (const float*)d_in[2];
    const float* w0s   = (const float*)d_in[3];   // (L,3,I,F,1)
    const float* w1s   = (const float*)d_in[4];   // (L,3,I,I,3)
    const float* w2s   = (const float*)d_in[5];   // (L,3,F,I,1)
    const float* out_w = (const float*)d_in[6];   // (C,2F,1)
    const float* out_b = (const float*)d_in[7];   // (C,)
    float* out = (float*)d_out;

    float *ph, *pt1, *pt2, *pdsh, *pstr, *plog;
    float *pw0t, *pw1t, *pw2t;
    cudaGetSymbolAddress((void**)&ph,   g_h);
    cudaGetSymbolAddress((void**)&pt1,  g_t1);
    cudaGetSymbolAddress((void**)&pt2,  g_t2);
    cudaGetSymbolAddress((void**)&pdsh, g_dsh);
    cudaGetSymbolAddress((void**)&pstr, g_str);
    cudaGetSymbolAddress((void**)&plog, g_logits);
    cudaGetSymbolAddress((void**)&pw0t, g_w0t);
    cudaGetSymbolAddress((void**)&pw1t, g_w1t);
    cudaGetSymbolAddress((void**)&pw2t, g_w2t);

    // batched pre-transpose of all conv weights (o-fastest layout), 3 launches
    const long n0 = (long)II * FF;          // per (l,j) w0
    const long n1 = (long)II * II * 3;      // per (l,j) w1
    const long n2 = (long)FF * II;          // per (l,j) w2
    transpose_w_b<<<(int)((6*n0 + 255)/256), 256>>>(w0s, pw0t, II, FF, 1, 6);
    transpose_w_b<<<(int)((6*n1 + 255)/256), 256>>>(w1s, pw1t, II, II, 3, 6);
    transpose_w_b<<<(int)((6*n2 + 255)/256), 256>>>(w2s, pw2t, FF, II, 1, 6);

    embed_kernel<<<(BB*SS*2*FF + 255)/256, 256>>>(inp, emb);

    const size_t NI = (size_t)BB * SS * II;   // per-j t-buffer stride
    const size_t NF = (size_t)BB * SS * FF;   // per-j dsh stride

    for (int l = 0; l < 2; l++) {
        h_kernel<<<(BB*SS*FF + 255)/256, 256>>>();
        conv_mma<FF, II, 1, true>
            <<<dim3(SS/128, II/128, 3*BB), 256>>>(ph,  0,  pw0t + l*3*n0, n0, pt1, NI);
        conv_mma<II, II, 3, true>
            <<<dim3(SS/128, II/128, 3*BB), 256>>>(pt1, NI, pw1t + l*3*n1, n1, pt2, NI);
        conv_mma<II, FF, 1, false>
            <<<dim3(SS/128, FF/128, 3*BB), 256>>>(pt2, NI, pw2t + l*3*n2, n2, pdsh, NF);
        cell_kernel<<<BB*SS, FF>>>();
    }

    concat_kernel<<<(BB*SS*2*FF + 255)/256, 256>>>();
    conv_gemm<2*FF, CC, 1, false, true>
        <<<dim3(SS/64, CC/64, BB), 256>>>(pstr, out_w, out_b, plog);

    nll_kernel<<<(BB*SS)/8, 256>>>(tgt);
    reduce_kernel<<<1, 256>>>(out);
}